// round 2
// baseline (speedup 1.0000x reference)
#include <cuda_runtime.h>
#include <cuda_bf16.h>

// KPConv fused kernel, fp32 baseline.
//   Stage 1: per-point neighbor geometry -> influence [K=32][Kp=15]
//   Stage 2: weighted[Kp][Cin] = sum_j infl[j][kp] * feats[nbr[j]][c]
//   Stage 3: out[d] = sum_{kp,c} weighted[kp][c] * W[kp][c][d]   (GEMM-like)
// Block processes TM=32 points; weighted tile kept in SMEM; stage 3 is
// register-blocked 4x4 per thread with per-kp 32KB weight tile in SMEM.

#define KNB   32      // neighbors per point
#define KP    15      // kernel points
#define CIN   64
#define COUT  128
#define TM    32      // points per block
#define NTHREADS 256
#define INV_SIGMA 10.0f   // 1/0.1

// smem layout (floats):
//   [0,48)           kernel points (15*3, padded)
//   [48,80)          neighbor indices (as int, 32)
//   [80,80+8192)     phase A: sInfl(480) + sF(2048)   | phase B: sWk(8192)
//   [80+8192, +30720) sWgt  (TM * 960)
#define SMEM_FLOATS (80 + 8192 + TM * (KP * CIN))
#define SMEM_BYTES  (SMEM_FLOATS * 4)

__device__ int g_idx64;   // 1 if neighbors are int64, 0 if int32

__global__ void detect_idx_kernel(const void* __restrict__ nbrs) {
    // Indices are in [0, 65536). If stored as int64 (little-endian), every
    // odd 32-bit word is 0. If int32, odd words are real indices (~never 0).
    const int* p = (const int*)nbrs;
    int zeros = 0;
#pragma unroll
    for (int i = 0; i < 32; i++) zeros += (p[2 * i + 1] == 0) ? 1 : 0;
    g_idx64 = (zeros >= 30) ? 1 : 0;
}

__global__ void __launch_bounds__(NTHREADS)
kpconv_kernel(const float* __restrict__ pos,
              const float* __restrict__ feats,
              const float* __restrict__ kpts,
              const float* __restrict__ W,
              const void*  __restrict__ nbrs,
              float* __restrict__ out,
              int N)
{
    extern __shared__ float smem[];
    float* sKP   = smem;                 // 48
    int*   sNbr  = (int*)(smem + 48);    // 32 ints
    float* sInfl = smem + 80;            // 480   (phase A)
    float* sF    = smem + 80 + (KP*KNB); // 2048  (phase A)
    float* sWk   = smem + 80;            // 8192  (phase B, reuses A region)
    float* sWgt  = smem + 80 + 8192;     // 30720

    const int tid  = threadIdx.x;
    const int base = blockIdx.x * TM;
    const int is64 = g_idx64;

    if (tid < KP * 3) sKP[tid] = kpts[tid];

    // ------------------------------ Phase A ------------------------------
    for (int p = 0; p < TM; p++) {
        const int n = base + p;
        __syncthreads();   // protect sInfl/sF/sNbr reuse vs previous iter

        if (n < N) {
            if (tid < KNB) {
                int nbi;
                if (is64) nbi = (int)((const long long*)nbrs)[(long long)n * KNB + tid];
                else      nbi = ((const int*)nbrs)[n * KNB + tid];
                sNbr[tid] = nbi;
                const float cx = pos[n * 3 + 0];
                const float cy = pos[n * 3 + 1];
                const float cz = pos[n * 3 + 2];
                const float rx = pos[nbi * 3 + 0] - cx;
                const float ry = pos[nbi * 3 + 1] - cy;
                const float rz = pos[nbi * 3 + 2] - cz;
#pragma unroll
                for (int kp = 0; kp < KP; kp++) {
                    const float dx = rx - sKP[kp * 3 + 0];
                    const float dy = ry - sKP[kp * 3 + 1];
                    const float dz = rz - sKP[kp * 3 + 2];
                    const float dist = sqrtf(dx * dx + dy * dy + dz * dz);
                    float infl = 1.0f - dist * INV_SIGMA;
                    sInfl[kp * KNB + tid] = infl > 0.0f ? infl : 0.0f;
                }
            }
        }
        __syncthreads();   // sNbr ready

        if (n < N) {
#pragma unroll
            for (int e = tid; e < KNB * CIN; e += NTHREADS) {
                const int j = e >> 6;
                const int c = e & 63;
                sF[e] = feats[sNbr[j] * CIN + c];
            }
        }
        __syncthreads();   // sF, sInfl ready

        // Stage 2: thread t -> c = t&63 fixed, kp in {t>>6, +4, +8, +12}
        if (n < N) {
            const int c   = tid & 63;
            const int kp0 = tid >> 6;          // 0..3
            float a0 = 0.f, a1 = 0.f, a2 = 0.f, a3 = 0.f;
            const float* iI = sInfl + kp0 * KNB;
#pragma unroll
            for (int j = 0; j < KNB; j++) {
                const float f = sF[j * CIN + c];
                a0 += iI[j]            * f;
                a1 += iI[4 * KNB + j]  * f;
                a2 += iI[8 * KNB + j]  * f;
                a3 += iI[12 * KNB + j] * f;   // kp0==3 -> kp 15, discarded below
            }
            float* g = sWgt + p * (KP * CIN);
            g[(kp0 + 0) * CIN + c] = a0;
            g[(kp0 + 4) * CIN + c] = a1;
            g[(kp0 + 8) * CIN + c] = a2;
            if (kp0 < 3) g[(kp0 + 12) * CIN + c] = a3;
        }
    }

    // ------------------------------ Phase B ------------------------------
    // 256 threads = 8 point-groups x 32 d-groups; thread tile = 4p x 4d.
    const int dg = tid & 31;
    const int pg = tid >> 5;

    float acc[4][4];
#pragma unroll
    for (int i = 0; i < 4; i++)
#pragma unroll
        for (int k = 0; k < 4; k++) acc[i][k] = 0.0f;

    for (int kp = 0; kp < KP; kp++) {
        __syncthreads();   // previous kp's sWk fully consumed (and phase A done)
#pragma unroll
        for (int e = tid; e < CIN * COUT; e += NTHREADS)
            sWk[e] = W[kp * (CIN * COUT) + e];
        __syncthreads();

        const float* g0 = sWgt + (pg * 4 + 0) * (KP * CIN) + kp * CIN;
        const float* g1 = g0 + (KP * CIN);
        const float* g2 = g1 + (KP * CIN);
        const float* g3 = g2 + (KP * CIN);
        const float* wk = sWk + dg * 4;

#pragma unroll 8
        for (int c = 0; c < CIN; c++) {
            const float4 wv = *(const float4*)(wk + c * COUT);
            const float b0 = g0[c];
            const float b1 = g1[c];
            const float b2 = g2[c];
            const float b3 = g3[c];
            acc[0][0] += b0 * wv.x; acc[0][1] += b0 * wv.y;
            acc[0][2] += b0 * wv.z; acc[0][3] += b0 * wv.w;
            acc[1][0] += b1 * wv.x; acc[1][1] += b1 * wv.y;
            acc[1][2] += b1 * wv.z; acc[1][3] += b1 * wv.w;
            acc[2][0] += b2 * wv.x; acc[2][1] += b2 * wv.y;
            acc[2][2] += b2 * wv.z; acc[2][3] += b2 * wv.w;
            acc[3][0] += b3 * wv.x; acc[3][1] += b3 * wv.y;
            acc[3][2] += b3 * wv.z; acc[3][3] += b3 * wv.w;
        }
    }

#pragma unroll
    for (int i = 0; i < 4; i++) {
        const int n = base + pg * 4 + i;
        if (n < N) {
            float4 v = make_float4(acc[i][0], acc[i][1], acc[i][2], acc[i][3]);
            *(float4*)(out + n * COUT + dg * 4) = v;
        }
    }
}

extern "C" void kernel_launch(void* const* d_in, const int* in_sizes, int n_in,
                              void* d_out, int out_size)
{
    const float* pos   = (const float*)d_in[0];
    const float* feats = (const float*)d_in[1];
    const float* kpts  = (const float*)d_in[2];
    const float* W     = (const float*)d_in[3];
    const void*  nbrs  = d_in[4];
    float* out = (float*)d_out;

    const int N = in_sizes[1] / CIN;   // feats is [N, CIN]

    // Opt in to >48KB dynamic smem (idempotent; immediate API, capture-safe).
    cudaFuncSetAttribute(kpconv_kernel,
                         cudaFuncAttributeMaxDynamicSharedMemorySize,
                         SMEM_BYTES);

    detect_idx_kernel<<<1, 1>>>(nbrs);

    const int blocks = (N + TM - 1) / TM;
    kpconv_kernel<<<blocks, NTHREADS, SMEM_BYTES>>>(pos, feats, kpts, W, nbrs, out, N);
}

// round 3
// speedup vs baseline: 2.8547x; 2.8547x over previous
#include <cuda_runtime.h>

// KPConv, 2-kernel decomposition:
//   stage12: per-point geometry + neighbor aggregation -> weighted[N][960]
//   stage3 : GEMM out[N][128] = weighted[N][960] @ W[960][128]
// Both use packed fp32 (fma.rn.f32x2, sm_100+) to halve FFMA issue count.

#define KNB   32
#define KP    15
#define CIN   64
#define COUT  128
#define KTOT  (KP * CIN)     // 960
#define NMAX  65536
#define INV_SIGMA 10.0f

typedef unsigned long long u64;
typedef unsigned int u32;

__device__ int g_idx64;                                   // neighbor dtype flag
__device__ float g_weighted[(size_t)NMAX * KTOT];         // 240MB scratch

__device__ __forceinline__ void fma2(u64& d, u64 a, u64 b) {
    asm("fma.rn.f32x2 %0, %1, %2, %0;" : "+l"(d) : "l"(a), "l"(b));
}
__device__ __forceinline__ u64 dup2(float x) {
    u64 r;
    asm("mov.b64 %0, {%1, %1};" : "=l"(r) : "r"(__float_as_uint(x)));
    return r;
}

__global__ void detect_idx_kernel(const void* __restrict__ nbrs) {
    // Indices < 2^16. int64 little-endian => odd 32-bit words are 0.
    const int* p = (const int*)nbrs;
    int zeros = 0;
#pragma unroll
    for (int i = 0; i < 32; i++) zeros += (p[2 * i + 1] == 0) ? 1 : 0;
    g_idx64 = (zeros >= 30) ? 1 : 0;
}

// ---------------------------------------------------------------- stage 1+2
// One warp per point. Lane j handles neighbor j for geometry; then lane l
// owns feature pair c = {2l, 2l+1} and accumulates 15 kp sums over 32 j.
__global__ void __launch_bounds__(256)
stage12_kernel(const float* __restrict__ pos,
               const float* __restrict__ feats,
               const float* __restrict__ kpts,
               const void*  __restrict__ nbrs,
               int N)
{
    __shared__ float  sKP[KP * 3];
    __shared__ int    sNbr[8][KNB];
    __shared__ float2 sInfl[8][KP * KNB];   // duplicated pairs {v,v}

    const int tid  = threadIdx.x;
    const int wid  = tid >> 5;
    const int lane = tid & 31;

    if (tid < KP * 3) sKP[tid] = kpts[tid];
    __syncthreads();

    const int n = blockIdx.x * 8 + wid;
    if (n >= N) return;

    // geometry: lane = neighbor j
    int nbi;
    if (g_idx64) nbi = (int)((const long long*)nbrs)[(long long)n * KNB + lane];
    else         nbi = ((const int*)nbrs)[n * KNB + lane];
    sNbr[wid][lane] = nbi;

    const float cx = pos[3 * n + 0];
    const float cy = pos[3 * n + 1];
    const float cz = pos[3 * n + 2];
    const float rx = pos[3 * nbi + 0] - cx;
    const float ry = pos[3 * nbi + 1] - cy;
    const float rz = pos[3 * nbi + 2] - cz;
#pragma unroll
    for (int kp = 0; kp < KP; kp++) {
        const float dx = rx - sKP[3 * kp + 0];
        const float dy = ry - sKP[3 * kp + 1];
        const float dz = rz - sKP[3 * kp + 2];
        const float dist = sqrtf(dx * dx + dy * dy + dz * dz);
        const float v = fmaxf(0.0f, 1.0f - dist * INV_SIGMA);
        sInfl[wid][kp * KNB + lane] = make_float2(v, v);
    }
    __syncwarp();

    // aggregation: lane owns c-pair {2*lane, 2*lane+1}
    u64 acc[KP];
#pragma unroll
    for (int kp = 0; kp < KP; kp++) acc[kp] = 0ULL;   // bits of {0.f,0.f}

#pragma unroll 4
    for (int j = 0; j < KNB; j++) {
        const int nb = sNbr[wid][j];
        const u64 f = *(const u64*)(feats + (size_t)nb * CIN + 2 * lane);
#pragma unroll
        for (int kp = 0; kp < KP; kp++) {
            const u64 s = *(const u64*)(&sInfl[wid][kp * KNB + j]); // broadcast
            fma2(acc[kp], s, f);
        }
    }

    float* gp = g_weighted + (size_t)n * KTOT + 2 * lane;
#pragma unroll
    for (int kp = 0; kp < KP; kp++)
        *(u64*)(gp + kp * CIN) = acc[kp];
}

// ------------------------------------------------------------------ stage 3
// out[N,128] = weighted[N,960] @ W[960,128]
// BM=128, BN=128, BK=8, 256 threads, 8x8 per thread, double-buffered smem.
// A is stored in smem as duplicated f32x2 pairs -> inner loop has zero MOVs:
// per k: 4x LDS.128 (a-dups) + 2x LDS.128 (b) + 32x FFMA2.
#define BM 128
#define BN 128
#define BK 8
#define S3_ITERS (KTOT / BK)   // 120

__global__ void __launch_bounds__(256)
stage3_kernel(const float* __restrict__ W,
              float* __restrict__ out,
              int N)
{
    __shared__ float2 As[2][BK][BM];   // duplicated pairs, 8KB per buf
    __shared__ float  Bs[2][BK][BN];   // 4KB per buf

    const int t  = threadIdx.x;
    const int tx = t & 15;     // n-group: 16 x 8 = 128
    const int ty = t >> 4;     // m-group: 16 x 8 = 128
    const int m0 = blockIdx.x * BM;

    // A global-load mapping: thread -> rows {arow, arow+64}, k-pair akp
    const int arow = t >> 2;
    const int akp  = (t & 3) * 2;
    const float* Abase = g_weighted + (size_t)m0 * KTOT;
    // B global-load mapping: thread -> k-row bk, 4 cols at bn
    const int bk = t >> 5;
    const int bn = (t & 31) * 4;

    float2 aR0, aR1;
    float4 bR;

    // prefetch tile 0
    aR0 = *(const float2*)(Abase + (size_t)arow * KTOT + akp);
    aR1 = *(const float2*)(Abase + (size_t)(arow + 64) * KTOT + akp);
    bR  = *(const float4*)(W + bk * COUT + bn);

    As[0][akp + 0][arow]      = make_float2(aR0.x, aR0.x);
    As[0][akp + 1][arow]      = make_float2(aR0.y, aR0.y);
    As[0][akp + 0][arow + 64] = make_float2(aR1.x, aR1.x);
    As[0][akp + 1][arow + 64] = make_float2(aR1.y, aR1.y);
    *(float4*)&Bs[0][bk][bn] = bR;
    __syncthreads();

    u64 acc[8][4];
#pragma unroll
    for (int i = 0; i < 8; i++)
#pragma unroll
        for (int p = 0; p < 4; p++) acc[i][p] = 0ULL;

    int buf = 0;
    for (int kt = 0; kt < S3_ITERS; kt++) {
        const int knext = (kt + 1) * BK;
        if (kt < S3_ITERS - 1) {
            aR0 = *(const float2*)(Abase + (size_t)arow * KTOT + knext + akp);
            aR1 = *(const float2*)(Abase + (size_t)(arow + 64) * KTOT + knext + akp);
            bR  = *(const float4*)(W + (knext + bk) * COUT + bn);
        }

#pragma unroll
        for (int k = 0; k < BK; k++) {
            // a-dups: 8 pairs = 4x 16B loads
            const u64* ap = (const u64*)&As[buf][k][ty * 8];
            u64 aa[8];
#pragma unroll
            for (int i = 0; i < 8; i++) aa[i] = ap[i];
            // b: 8 floats = 4 n-pairs
            const u64* bp = (const u64*)&Bs[buf][k][tx * 8];
            u64 bb[4];
#pragma unroll
            for (int p = 0; p < 4; p++) bb[p] = bp[p];
#pragma unroll
            for (int i = 0; i < 8; i++)
#pragma unroll
                for (int p = 0; p < 4; p++)
                    fma2(acc[i][p], aa[i], bb[p]);
        }

        if (kt < S3_ITERS - 1) {
            const int nb = buf ^ 1;
            As[nb][akp + 0][arow]      = make_float2(aR0.x, aR0.x);
            As[nb][akp + 1][arow]      = make_float2(aR0.y, aR0.y);
            As[nb][akp + 0][arow + 64] = make_float2(aR1.x, aR1.x);
            As[nb][akp + 1][arow + 64] = make_float2(aR1.y, aR1.y);
            *(float4*)&Bs[nb][bk][bn] = bR;
            __syncthreads();
            buf = nb;
        }
    }

    // epilogue: acc[i][p] is the n-pair {tx*8+2p, tx*8+2p+1} of row m0+ty*8+i
#pragma unroll
    for (int i = 0; i < 8; i++) {
        const int m = m0 + ty * 8 + i;
        if (m < N) {
            float2* op = (float2*)(out + (size_t)m * COUT + tx * 8);
#pragma unroll
            for (int p = 0; p < 4; p++) {
                float2 v;
                v.x = __uint_as_float((u32)(acc[i][p] & 0xFFFFFFFFULL));
                v.y = __uint_as_float((u32)(acc[i][p] >> 32));
                op[p] = v;
            }
        }
    }
}

extern "C" void kernel_launch(void* const* d_in, const int* in_sizes, int n_in,
                              void* d_out, int out_size)
{
    const float* pos   = (const float*)d_in[0];
    const float* feats = (const float*)d_in[1];
    const float* kpts  = (const float*)d_in[2];
    const float* W     = (const float*)d_in[3];
    const void*  nbrs  = d_in[4];
    float* out = (float*)d_out;

    const int N = in_sizes[1] / CIN;   // feats is [N, CIN]

    detect_idx_kernel<<<1, 1>>>(nbrs);

    const int blocksA = (N + 7) / 8;
    stage12_kernel<<<blocksA, 256>>>(pos, feats, kpts, nbrs, N);

    const int blocksB = (N + BM - 1) / BM;
    stage3_kernel<<<blocksB, 256>>>(W, out, N);
}

// round 7
// speedup vs baseline: 3.8641x; 1.3536x over previous
#include <cuda_runtime.h>
#include <cstdint>

#define KNB   32
#define KP    15
#define CIN   64
#define COUT  128
#define KTOT  (KP * CIN)     // 960
#define NMAX  65536
#define INV_SIGMA 10.0f

typedef unsigned long long u64;
typedef unsigned int u32;

__device__ float g_weighted[(size_t)NMAX * KTOT];   // 240MB scratch (tf32-rounded)
__device__ float g_Wt[COUT * KTOT];                 // W transposed [n][k], tf32-rounded

__device__ __forceinline__ void fma2(u64& d, u64 a, u64 b) {
    asm("fma.rn.f32x2 %0, %1, %2, %0;" : "+l"(d) : "l"(a), "l"(b));
}
__device__ __forceinline__ u32 tf32r(float x) {
    u32 r;
    asm("cvt.rna.tf32.f32 %0, %1;" : "=r"(r) : "f"(x));
    return r;
}

// ------------------------------------------------------------ W transpose (+tf32 round)
__global__ void wt_kernel(const float* __restrict__ W) {
    int i = blockIdx.x * 256 + threadIdx.x;     // over KTOT*COUT
    if (i < KTOT * COUT) {
        int k = i >> 7;          // KTOT index
        int n = i & 127;         // COUT index
        ((u32*)g_Wt)[n * KTOT + k] = tf32r(W[i]);
    }
}

// ---------------------------------------------------------------- stage 1+2
// One warp per point; lane j = neighbor for geometry; then lane owns c-pair.
__global__ void __launch_bounds__(256)
stage12_kernel(const float* __restrict__ pos,
               const float* __restrict__ feats,
               const float* __restrict__ kpts,
               const void*  __restrict__ nbrs,
               int N)
{
    __shared__ float  sKP[KP * 3];
    __shared__ int    sNbr[8][KNB];
    __shared__ float2 sInfl[8][KP * KNB];
    __shared__ int    sIs64;

    const int tid  = threadIdx.x;
    const int wid  = tid >> 5;
    const int lane = tid & 31;

    if (tid < KP * 3) sKP[tid] = kpts[tid];
    if (tid == 0) {
        // indices < 2^16: int64 little-endian => odd 32-bit words are 0
        const int* p = (const int*)nbrs;
        int zeros = 0;
#pragma unroll
        for (int i = 0; i < 32; i++) zeros += (p[2 * i + 1] == 0) ? 1 : 0;
        sIs64 = (zeros >= 30) ? 1 : 0;
    }
    __syncthreads();

    const int n = blockIdx.x * 8 + wid;
    if (n >= N) return;

    int nbi;
    if (sIs64) nbi = (int)((const long long*)nbrs)[(long long)n * KNB + lane];
    else       nbi = ((const int*)nbrs)[n * KNB + lane];
    sNbr[wid][lane] = nbi;

    const float cx = pos[3 * n + 0];
    const float cy = pos[3 * n + 1];
    const float cz = pos[3 * n + 2];
    const float rx = pos[3 * nbi + 0] - cx;
    const float ry = pos[3 * nbi + 1] - cy;
    const float rz = pos[3 * nbi + 2] - cz;
#pragma unroll
    for (int kp = 0; kp < KP; kp++) {
        const float dx = rx - sKP[3 * kp + 0];
        const float dy = ry - sKP[3 * kp + 1];
        const float dz = rz - sKP[3 * kp + 2];
        const float dist = sqrtf(dx * dx + dy * dy + dz * dz);
        const float v = fmaxf(0.0f, 1.0f - dist * INV_SIGMA);
        sInfl[wid][kp * KNB + lane] = make_float2(v, v);
    }
    __syncwarp();

    u64 acc[KP];
#pragma unroll
    for (int kp = 0; kp < KP; kp++) acc[kp] = 0ULL;

#pragma unroll 4
    for (int j = 0; j < KNB; j++) {
        const int nb = sNbr[wid][j];
        const u64 f = *(const u64*)(feats + (size_t)nb * CIN + 2 * lane);
#pragma unroll
        for (int kp = 0; kp < KP; kp++) {
            const u64 s = *(const u64*)(&sInfl[wid][kp * KNB + j]);
            fma2(acc[kp], s, f);
        }
    }

    // store tf32-rounded so stage3's HMMA sees RN-rounded tf32 inputs
    u32* gp = (u32*)(g_weighted + (size_t)n * KTOT + 2 * lane);
#pragma unroll
    for (int kp = 0; kp < KP; kp++) {
        const u32 lo = tf32r(__uint_as_float((u32)(acc[kp] & 0xFFFFFFFFULL)));
        const u32 hi = tf32r(__uint_as_float((u32)(acc[kp] >> 32)));
        u64 pk = ((u64)hi << 32) | lo;
        *(u64*)(gp + kp * CIN) = pk;
    }
}

// ------------------------------------------------------------------ stage 3
// out[N,128] = g_weighted[N,960] @ g_Wt^T  via mma.sync m16n8k8 tf32.
// CTA 128x128, K chunks of 32 (4 k8-steps), double-buffered smem.
// Smem per k8-step plane: [128 rows][8 k-interleaved], pos = 2*(k&3)+(k>>2),
// so fragment cols {c, c+4} are adjacent -> one lds.64 per fragment pair.
#define NC 30

__device__ __forceinline__ void mma_tf32(float* c, u32 a0, u32 a1, u32 a2, u32 a3,
                                         u32 b0, u32 b1) {
    asm("mma.sync.aligned.m16n8k8.row.col.f32.tf32.tf32.f32 "
        "{%0,%1,%2,%3}, {%4,%5,%6,%7}, {%8,%9}, {%0,%1,%2,%3};"
        : "+f"(c[0]), "+f"(c[1]), "+f"(c[2]), "+f"(c[3])
        : "r"(a0), "r"(a1), "r"(a2), "r"(a3), "r"(b0), "r"(b1));
}

__global__ void __launch_bounds__(256)
stage3_hmma(float* __restrict__ out, int N)
{
    extern __shared__ float sm[];   // As [2][4][128][8] @0 ; Bs same @8192
    const int tid  = threadIdx.x;
    const int w    = tid >> 5;
    const int lane = tid & 31;
    const int wm   = (w & 1) * 64;
    const int wn   = (w >> 1) * 32;
    const int m0   = blockIdx.x * 128;

    // global load mapping: thread -> row = tid>>1, 16 floats at hf
    const int row = tid >> 1;
    const int hf  = (tid & 1) * 16;
    const float* Ab = g_weighted + (size_t)(m0 + row) * KTOT + hf;
    const float* Bb = g_Wt + (size_t)row * KTOT + hf;

    float acc[4][4][4];
#pragma unroll
    for (int mt = 0; mt < 4; mt++)
#pragma unroll
        for (int nt = 0; nt < 4; nt++)
#pragma unroll
            for (int q = 0; q < 4; q++) acc[mt][nt][q] = 0.0f;

    float4 ar[4], br[4];

    // prefetch + stage chunk 0
#pragma unroll
    for (int i = 0; i < 4; i++) {
        ar[i] = *(const float4*)(Ab + i * 4);
        br[i] = *(const float4*)(Bb + i * 4);
    }
#pragma unroll
    for (int i = 0; i < 4; i++) {
        const int k0 = hf + i * 4;
        const int s  = k0 >> 3;
        const int bp = (k0 >> 2) & 1;
        float* Ad = sm + s * 1024 + row * 8 + bp;
        float* Bd = sm + 8192 + s * 1024 + row * 8 + bp;
        Ad[0] = ar[i].x; Ad[2] = ar[i].y; Ad[4] = ar[i].z; Ad[6] = ar[i].w;
        Bd[0] = br[i].x; Bd[2] = br[i].y; Bd[4] = br[i].z; Bd[6] = br[i].w;
    }
    __syncthreads();

    for (int c = 0; c < NC; c++) {
        const int cur = c & 1;
        if (c + 1 < NC) {
            const int ko = (c + 1) * 32;
#pragma unroll
            for (int i = 0; i < 4; i++) {
                ar[i] = *(const float4*)(Ab + ko + i * 4);
                br[i] = *(const float4*)(Bb + ko + i * 4);
            }
        }

        // compute on buffer cur: 4 k8-steps
#pragma unroll
        for (int s = 0; s < 4; s++) {
            const float* Abase = sm + cur * 4096 + s * 1024;
            const float* Bbase = sm + 8192 + cur * 4096 + s * 1024;
            u32 a[4][4];
#pragma unroll
            for (int mt = 0; mt < 4; mt++) {
                const int r0 = wm + mt * 16 + (lane >> 2);
                const uint2 lo = *(const uint2*)(Abase + r0 * 8 + 2 * (lane & 3));
                const uint2 hi = *(const uint2*)(Abase + (r0 + 8) * 8 + 2 * (lane & 3));
                a[mt][0] = lo.x; a[mt][1] = hi.x; a[mt][2] = lo.y; a[mt][3] = hi.y;
            }
#pragma unroll
            for (int nt = 0; nt < 4; nt++) {
                const int n = wn + nt * 8 + (lane >> 2);
                const uint2 bb = *(const uint2*)(Bbase + n * 8 + 2 * (lane & 3));
#pragma unroll
                for (int mt = 0; mt < 4; mt++)
                    mma_tf32(acc[mt][nt], a[mt][0], a[mt][1], a[mt][2], a[mt][3],
                             bb.x, bb.y);
            }
        }

        if (c + 1 < NC) {
            const int nxt = cur ^ 1;
#pragma unroll
            for (int i = 0; i < 4; i++) {
                const int k0 = hf + i * 4;
                const int s  = k0 >> 3;
                const int bp = (k0 >> 2) & 1;
                float* Ad = sm + nxt * 4096 + s * 1024 + row * 8 + bp;
                float* Bd = sm + 8192 + nxt * 4096 + s * 1024 + row * 8 + bp;
                Ad[0] = ar[i].x; Ad[2] = ar[i].y; Ad[4] = ar[i].z; Ad[6] = ar[i].w;
                Bd[0] = br[i].x; Bd[2] = br[i].y; Bd[4] = br[i].z; Bd[6] = br[i].w;
            }
            __syncthreads();
        }
    }

    // epilogue: c0,c1 -> (row, 2c+{0,1}); c2,c3 -> row+8
#pragma unroll
    for (int mt = 0; mt < 4; mt++) {
        const int r0 = m0 + wm + mt * 16 + (lane >> 2);
#pragma unroll
        for (int nt = 0; nt < 4; nt++) {
            const int n = wn + nt * 8 + 2 * (lane & 3);
            if (r0 < N)
                *(float2*)(out + (size_t)r0 * COUT + n) =
                    make_float2(acc[mt][nt][0], acc[mt][nt][1]);
            if (r0 + 8 < N)
                *(float2*)(out + (size_t)(r0 + 8) * COUT + n) =
                    make_float2(acc[mt][nt][2], acc[mt][nt][3]);
        }
    }
}

extern "C" void kernel_launch(void* const* d_in, const int* in_sizes, int n_in,
                              void* d_out, int out_size)
{
    const float* pos   = (const float*)d_in[0];
    const float* feats = (const float*)d_in[1];
    const float* kpts  = (const float*)d_in[2];
    const float* W     = (const float*)d_in[3];
    const void*  nbrs  = d_in[4];
    float* out = (float*)d_out;

    const int N = in_sizes[1] / CIN;   // feats is [N, CIN]

    const int SMEM = 2 * 4096 * 2 * 4;   // 64KB
    cudaFuncSetAttribute(stage3_hmma,
                         cudaFuncAttributeMaxDynamicSharedMemorySize, SMEM);

    wt_kernel<<<(KTOT * COUT + 255) / 256, 256>>>(W);

    stage12_kernel<<<(N + 7) / 8, 256>>>(pos, feats, kpts, nbrs, N);

    stage3_hmma<<<(N + 127) / 128, 256, SMEM>>>(out, N);
}